// round 2
// baseline (speedup 1.0000x reference)
#include <cuda_runtime.h>
#include <cuda_bf16.h>

// Model dims
#define SEQ 1024
#define DM  768
#define NL  12
#define NH  24
#define DK  32
#define DV  32
#define QKV_OUT 2304   // NH*(DK+DK+DV)
#define FF_IN 1536     // 2*DM
#define VSZ 50304

// ---------------- device scratch (no mallocs allowed) ----------------
__device__ float g_x  [SEQ * DM];
__device__ float g_ln [SEQ * DM];
__device__ float g_buf[SEQ * QKV_OUT];   // qkv output / pos-mlp output (1024x1536 fits)
__device__ float g_att[SEQ * DM];
__device__ float g_z  [SEQ * FF_IN];
__device__ float g_z2 [SEQ * DM];

// ---------------- embedding ----------------
__global__ void embed_kernel(const int* __restrict__ tok,
                             const float* __restrict__ ew,
                             float* __restrict__ x) {
    int t = blockIdx.x;           // 1024
    int d = threadIdx.x;          // 768
    x[t * DM + d] = ew[(size_t)tok[t] * DM + d];
}

// ---------------- positional log-space scan ----------------
// h: (SEQ, 1536)  h[:, :768] -> log_sigmoid coeffs, h[:, 768:] -> logits
// x[t,d] += a_star[t+1] + logcumsumexp_{s<=t+1}(prepended[s] - a_star[s])
__global__ void pos_scan_kernel(const float* __restrict__ h,
                                float* __restrict__ x) {
    int d = blockIdx.x * blockDim.x + threadIdx.x;   // 768 channels
    if (d >= DM) return;
    float A = 0.f;
    float m = 0.f;   // logaddexp accumulator; t=0 term is (0 - 0) = 0
    for (int t = 0; t < SEQ; t++) {
        float hv = h[t * FF_IN + d];
        float lg = h[t * FF_IN + DM + d];
        // log_sigmoid(hv)
        float lc = (hv > 0.f) ? -log1pf(expf(-hv)) : hv - log1pf(expf(hv));
        A += lc;
        float v = lg - A;
        float mx = fmaxf(m, v), mn = fminf(m, v);
        m = mx + log1pf(expf(mn - mx));
        x[t * DM + d] += A + m;
    }
}

// ---------------- layernorm ----------------
__device__ __forceinline__ float warp_sum(float v) {
#pragma unroll
    for (int o = 16; o; o >>= 1) v += __shfl_xor_sync(0xffffffffu, v, o);
    return v;
}

__global__ __launch_bounds__(256) void layernorm_kernel(
    const float* __restrict__ x, const float* __restrict__ g,
    const float* __restrict__ b, float* __restrict__ out) {
    int t = blockIdx.x;
    int tid = threadIdx.x;
    const float* row = x + t * DM;
    float v0 = row[tid], v1 = row[tid + 256], v2 = row[tid + 512];

    __shared__ float red[8];
    __shared__ float s_mean, s_rstd;

    float s = v0 + v1 + v2;
    s = warp_sum(s);
    if ((tid & 31) == 0) red[tid >> 5] = s;
    __syncthreads();
    if (tid < 32) {
        float r = (tid < 8) ? red[tid] : 0.f;
        r = warp_sum(r);
        if (tid == 0) s_mean = r * (1.f / DM);
    }
    __syncthreads();
    float mean = s_mean;
    float d0 = v0 - mean, d1 = v1 - mean, d2 = v2 - mean;
    float q = d0 * d0 + d1 * d1 + d2 * d2;
    q = warp_sum(q);
    if ((tid & 31) == 0) red[tid >> 5] = q;
    __syncthreads();
    if (tid < 32) {
        float r = (tid < 8) ? red[tid] : 0.f;
        r = warp_sum(r);
        if (tid == 0) s_rstd = rsqrtf(r * (1.f / DM) + 1e-5f);
    }
    __syncthreads();
    float rs = s_rstd;
    out[t * DM + tid]       = d0 * rs * g[tid]       + b[tid];
    out[t * DM + tid + 256] = d1 * rs * g[tid + 256] + b[tid + 256];
    out[t * DM + tid + 512] = d2 * rs * g[tid + 512] + b[tid + 512];
}

// ---------------- generic tiled fp32 GEMM ----------------
// C[M,N] = A[M,K] @ B  (+bias) (+accumulate into C)
// TRANSB=false: B is (K,N) row-major.  TRANSB=true: B is (N,K) row-major.
// Requires M%64==0, N%64==0, K%16==0 (true for all shapes here).
template<bool TRANSB, bool BIAS, bool ACCUM>
__global__ __launch_bounds__(256) void gemm_kernel(
    const float* __restrict__ A, const float* __restrict__ B,
    const float* __restrict__ bias, float* __restrict__ C,
    int M, int N, int K) {
    __shared__ float As[16][68];
    __shared__ float Bs[16][68];
    int tid = threadIdx.x;
    int n0 = blockIdx.x * 64, m0 = blockIdx.y * 64;
    int tx = tid & 15, ty = tid >> 4;
    int lm = tid >> 2;             // 0..63
    int lk = (tid & 3) << 2;       // 0,4,8,12

    float acc[4][4];
#pragma unroll
    for (int i = 0; i < 4; i++)
#pragma unroll
        for (int j = 0; j < 4; j++) acc[i][j] = 0.f;

    const float* Ap = A + (size_t)(m0 + lm) * K + lk;
    const float* Bp = TRANSB ? (B + (size_t)(n0 + lm) * K + lk) : B;

    for (int k0 = 0; k0 < K; k0 += 16) {
        float4 a4 = *(const float4*)(Ap + k0);
        As[lk + 0][lm] = a4.x; As[lk + 1][lm] = a4.y;
        As[lk + 2][lm] = a4.z; As[lk + 3][lm] = a4.w;
        if (TRANSB) {
            float4 b4 = *(const float4*)(Bp + k0);
            Bs[lk + 0][lm] = b4.x; Bs[lk + 1][lm] = b4.y;
            Bs[lk + 2][lm] = b4.z; Bs[lk + 3][lm] = b4.w;
        } else {
            int bn = tid & 63, bk = tid >> 6;
#pragma unroll
            for (int r = 0; r < 4; r++)
                Bs[bk + 4 * r][bn] = B[(size_t)(k0 + bk + 4 * r) * N + n0 + bn];
        }
        __syncthreads();
#pragma unroll
        for (int kk = 0; kk < 16; kk++) {
            float4 av = *(const float4*)&As[kk][ty << 2];
            float4 bv = *(const float4*)&Bs[kk][tx << 2];
            float a_[4] = {av.x, av.y, av.z, av.w};
            float b_[4] = {bv.x, bv.y, bv.z, bv.w};
#pragma unroll
            for (int i = 0; i < 4; i++)
#pragma unroll
                for (int j = 0; j < 4; j++) acc[i][j] += a_[i] * b_[j];
        }
        __syncthreads();
    }
    // epilogue: cols n0 + (tx<<2) .. +3 are 16B-aligned -> float4 stores
#pragma unroll
    for (int i = 0; i < 4; i++) {
        int row = m0 + (ty << 2) + i;
        int col = n0 + (tx << 2);
        float4 v = make_float4(acc[i][0], acc[i][1], acc[i][2], acc[i][3]);
        if (BIAS) {
            const float4 bv = *(const float4*)(bias + col);
            v.x += bv.x; v.y += bv.y; v.z += bv.z; v.w += bv.w;
        }
        float* cp = C + (size_t)row * N + col;
        if (ACCUM) {
            float4 o = *(const float4*)cp;
            v.x += o.x; v.y += o.y; v.z += o.z; v.w += o.w;
        }
        *(float4*)cp = v;
    }
}

// ---------------- attention (exp-space causal linear attention) ----------------
// exp(log_S[t,j]) = sum_{s<=t} w_ts * e^{V_sj},  w_ts = sum_i e^{Q_ti + K_si}
// exp(log_Z[t])   = sum_{s<=t} w_ts
// att[t, h*32+j] = log S - log Z
// One block per (row-chunk of 64, head). 256 threads.
__global__ __launch_bounds__(256) void attn_kernel(
    const float* __restrict__ qkv, float* __restrict__ att) {
    int c = blockIdx.x;       // row chunk 0..15
    int h = blockIdx.y;       // head
    int tid = threadIdx.x;

    __shared__ float EQ[64][36];
    __shared__ float EK[64][36];
    __shared__ float EV[64][36];
    __shared__ float W [64][65];

    int t0 = c * 64;
    // load EQ (exp applied)
    for (int e = tid; e < 64 * 32; e += 256) {
        int r = e >> 5, k = e & 31;
        EQ[r][k] = expf(qkv[(size_t)(t0 + r) * QKV_OUT + h * 96 + k]);
    }

    float S[8];
#pragma unroll
    for (int u = 0; u < 8; u++) S[u] = 0.f;
    float z = 0.f;

    int rr = tid >> 2;         // row (both phases)
    int q4 = tid & 3;          // lane-in-quad
    int tc = q4 * 8;           // col group for S phase

    __syncthreads();

    for (int sc = 0; sc <= c; sc++) {
        int s0 = sc * 64;
        for (int e = tid; e < 64 * 32; e += 256) {
            int r = e >> 5, k = e & 31;
            const float* p = &qkv[(size_t)(s0 + r) * QKV_OUT + h * 96 + 32 + k];
            EK[r][k] = expf(p[0]);
            EV[r][k] = expf(p[32]);
        }
        __syncthreads();

        // build W: thread covers row rr, cols s = 4*ss + q4
        {
            float accw[16];
#pragma unroll
            for (int ss = 0; ss < 16; ss++) accw[ss] = 0.f;
#pragma unroll
            for (int k0 = 0; k0 < 32; k0 += 4) {
                float4 q = *(const float4*)&EQ[rr][k0];
#pragma unroll
                for (int ss = 0; ss < 16; ss++) {
                    float4 e = *(const float4*)&EK[4 * ss + q4][k0];
                    accw[ss] += q.x * e.x + q.y * e.y + q.z * e.z + q.w * e.w;
                }
            }
            bool diag = (sc == c);
#pragma unroll
            for (int ss = 0; ss < 16; ss++) {
                int s = 4 * ss + q4;
                W[rr][s] = (diag && s > rr) ? 0.f : accw[ss];
            }
        }
        __syncthreads();

        // S += W @ EV ; z += rowsum(W)
#pragma unroll 4
        for (int s = 0; s < 64; s++) {
            float w = W[rr][s];
            z += w;
            float4 e0 = *(const float4*)&EV[s][tc];
            float4 e1 = *(const float4*)&EV[s][tc + 4];
            S[0] += w * e0.x; S[1] += w * e0.y; S[2] += w * e0.z; S[3] += w * e0.w;
            S[4] += w * e1.x; S[5] += w * e1.y; S[6] += w * e1.z; S[7] += w * e1.w;
        }
        __syncthreads();
    }

    float lz = logf(z);
    float* o = &att[(size_t)(t0 + rr) * DM + h * 32 + tc];
#pragma unroll
    for (int u = 0; u < 8; u++) o[u] = logf(S[u]) - lz;
}

// ---------------- GLU ----------------
__global__ void glu_kernel(const float* __restrict__ zin, float* __restrict__ zout) {
    int t = blockIdx.x, d = threadIdx.x;   // 1024 x 768
    float a = zin[t * FF_IN + d];
    float b = zin[t * FF_IN + DM + d];
    zout[t * DM + d] = a * (1.f / (1.f + expf(-b)));
}

// ---------------- launch ----------------
extern "C" void kernel_launch(void* const* d_in, const int* in_sizes, int n_in,
                              void* d_out, int out_size) {
    const int*   tok     = (const int*)  d_in[0];
    const float* embed_w = (const float*)d_in[1];
    const float* pos_w   = (const float*)d_in[2];
    const float* pos_b   = (const float*)d_in[3];
    const float* ln1_g   = (const float*)d_in[4];
    const float* ln1_b   = (const float*)d_in[5];
    const float* qkv_w   = (const float*)d_in[6];
    const float* qkv_b   = (const float*)d_in[7];
    const float* ff_w1   = (const float*)d_in[8];
    const float* ff_b1   = (const float*)d_in[9];
    const float* ff_w2   = (const float*)d_in[10];
    const float* lnf_g   = (const float*)d_in[11];
    const float* lnf_b   = (const float*)d_in[12];

    float *x, *ln, *buf, *att, *z, *z2;
    cudaGetSymbolAddress((void**)&x,   g_x);
    cudaGetSymbolAddress((void**)&ln,  g_ln);
    cudaGetSymbolAddress((void**)&buf, g_buf);
    cudaGetSymbolAddress((void**)&att, g_att);
    cudaGetSymbolAddress((void**)&z,   g_z);
    cudaGetSymbolAddress((void**)&z2,  g_z2);

    cudaStream_t st = cudaStreamPerThread;

    // x = embed_w[token_ids]
    embed_kernel<<<SEQ, DM, 0, st>>>(tok, embed_w, x);

    // h = x @ pos_w + pos_b  -> buf (1024 x 1536)
    gemm_kernel<false, true, false><<<dim3(FF_IN / 64, SEQ / 64), 256, 0, st>>>(
        x, pos_w, pos_b, buf, SEQ, FF_IN, DM);

    // x += positional recurrence
    pos_scan_kernel<<<6, 128, 0, st>>>(buf, x);

    for (int l = 0; l < NL; l++) {
        layernorm_kernel<<<SEQ, 256, 0, st>>>(x, ln1_g + l * DM, ln1_b + l * DM, ln);

        gemm_kernel<false, true, false><<<dim3(QKV_OUT / 64, SEQ / 64), 256, 0, st>>>(
            ln, qkv_w + (size_t)l * DM * QKV_OUT, qkv_b + l * QKV_OUT, buf,
            SEQ, QKV_OUT, DM);

        attn_kernel<<<dim3(16, NH), 256, 0, st>>>(buf, att);

        gemm_kernel<false, true, false><<<dim3(FF_IN / 64, SEQ / 64), 256, 0, st>>>(
            att, ff_w1 + (size_t)l * DM * FF_IN, ff_b1 + l * FF_IN, z,
            SEQ, FF_IN, DM);

        glu_kernel<<<SEQ, DM, 0, st>>>(z, z2);

        gemm_kernel<false, false, true><<<dim3(DM / 64, SEQ / 64), 256, 0, st>>>(
            z2, ff_w2 + (size_t)l * DM * DM, nullptr, x, SEQ, DM, DM);
    }

    layernorm_kernel<<<SEQ, 256, 0, st>>>(x, lnf_g, lnf_b, ln);

    // logits = ln @ embed_w^T  (NT GEMM, 1024 x 50304 x 768)
    gemm_kernel<true, false, false><<<dim3(VSZ / 64, SEQ / 64), 256, 0, st>>>(
        ln, embed_w, nullptr, (float*)d_out, SEQ, VSZ, DM);
}

// round 3
// speedup vs baseline: 1.7184x; 1.7184x over previous
#include <cuda_runtime.h>
#include <cuda_bf16.h>

// Model dims
#define SEQ 1024
#define DM  768
#define NL  12
#define NH  24
#define DK  32
#define DV  32
#define QKV_OUT 2304   // NH*(DK+DK+DV)
#define FF_IN 1536     // 2*DM
#define VSZ 50304

// ---------------- device scratch (no mallocs allowed) ----------------
__device__ float g_x  [SEQ * DM];
__device__ float g_ln [SEQ * DM];
__device__ float g_buf[SEQ * QKV_OUT];
__device__ float g_att[SEQ * DM];
__device__ float g_z  [SEQ * FF_IN];
__device__ float g_z2 [SEQ * DM];

// transposed weights (N,K) for mma row.col
#define QKVT_OFF 0
#define FF1T_OFF (12 * QKV_OUT * DM)
#define FF2T_OFF (FF1T_OFF + 12 * FF_IN * DM)
#define POST_OFF (FF2T_OFF + 12 * DM * DM)
#define WT_TOTAL (POST_OFF + FF_IN * DM)
__device__ float g_wT[WT_TOTAL];

// ---------------- helpers ----------------
__device__ __forceinline__ unsigned tf32r(float x) {
    unsigned u; asm("cvt.rna.tf32.f32 %0, %1;" : "=r"(u) : "f"(x)); return u;
}
__device__ __forceinline__ void cpasync16(void* smem_dst, const void* gsrc) {
    unsigned d = (unsigned)__cvta_generic_to_shared(smem_dst);
    asm volatile("cp.async.ca.shared.global [%0], [%1], 16;" :: "r"(d), "l"(gsrc));
}
__device__ __forceinline__ void mma8(float* c, const unsigned* a, const unsigned* b) {
    asm volatile(
        "mma.sync.aligned.m16n8k8.row.col.f32.tf32.tf32.f32 "
        "{%0,%1,%2,%3}, {%4,%5,%6,%7}, {%8,%9}, {%0,%1,%2,%3};"
        : "+f"(c[0]), "+f"(c[1]), "+f"(c[2]), "+f"(c[3])
        : "r"(a[0]), "r"(a[1]), "r"(a[2]), "r"(a[3]), "r"(b[0]), "r"(b[1]));
}

// ---------------- embedding ----------------
__global__ void embed_kernel(const int* __restrict__ tok,
                             const float* __restrict__ ew,
                             float* __restrict__ x) {
    int t = blockIdx.x, d = threadIdx.x;
    x[t * DM + d] = ew[(size_t)tok[t] * DM + d];
}

// ---------------- weight transpose (R,C) -> (C,R), batched ----------------
__global__ void transpose_kernel(const float* __restrict__ in,
                                 float* __restrict__ out, int R, int C) {
    __shared__ float tile[32][33];
    size_t off = (size_t)blockIdx.z * R * C;
    const float* src = in + off;
    float* dst = out + off;
    int c0 = blockIdx.x * 32, r0 = blockIdx.y * 32;
    int x = threadIdx.x, y = threadIdx.y;
#pragma unroll
    for (int j = 0; j < 32; j += 8)
        tile[y + j][x] = src[(size_t)(r0 + y + j) * C + c0 + x];
    __syncthreads();
#pragma unroll
    for (int j = 0; j < 32; j += 8)
        dst[(size_t)(c0 + y + j) * R + r0 + x] = tile[x][y + j];
}

// ---------------- positional log-space scan ----------------
__global__ void pos_scan_kernel(const float* __restrict__ h,
                                float* __restrict__ x) {
    int d = blockIdx.x * blockDim.x + threadIdx.x;
    if (d >= DM) return;
    float A = 0.f;
    float m = 0.f;
    for (int t = 0; t < SEQ; t++) {
        float hv = h[t * FF_IN + d];
        float lg = h[t * FF_IN + DM + d];
        float lc = (hv > 0.f) ? -log1pf(expf(-hv)) : hv - log1pf(expf(hv));
        A += lc;
        float v = lg - A;
        float mx = fmaxf(m, v), mn = fminf(m, v);
        m = mx + log1pf(expf(mn - mx));
        x[t * DM + d] += A + m;
    }
}

// ---------------- layernorm ----------------
__device__ __forceinline__ float warp_sum(float v) {
#pragma unroll
    for (int o = 16; o; o >>= 1) v += __shfl_xor_sync(0xffffffffu, v, o);
    return v;
}

__global__ __launch_bounds__(256) void layernorm_kernel(
    const float* __restrict__ x, const float* __restrict__ g,
    const float* __restrict__ b, float* __restrict__ out) {
    int t = blockIdx.x;
    int tid = threadIdx.x;
    const float* row = x + t * DM;
    float v0 = row[tid], v1 = row[tid + 256], v2 = row[tid + 512];

    __shared__ float red[8];
    __shared__ float s_mean, s_rstd;

    float s = v0 + v1 + v2;
    s = warp_sum(s);
    if ((tid & 31) == 0) red[tid >> 5] = s;
    __syncthreads();
    if (tid < 32) {
        float r = (tid < 8) ? red[tid] : 0.f;
        r = warp_sum(r);
        if (tid == 0) s_mean = r * (1.f / DM);
    }
    __syncthreads();
    float mean = s_mean;
    float d0 = v0 - mean, d1 = v1 - mean, d2 = v2 - mean;
    float q = d0 * d0 + d1 * d1 + d2 * d2;
    q = warp_sum(q);
    if ((tid & 31) == 0) red[tid >> 5] = q;
    __syncthreads();
    if (tid < 32) {
        float r = (tid < 8) ? red[tid] : 0.f;
        r = warp_sum(r);
        if (tid == 0) s_rstd = rsqrtf(r * (1.f / DM) + 1e-5f);
    }
    __syncthreads();
    float rs = s_rstd;
    out[t * DM + tid]       = d0 * rs * g[tid]       + b[tid];
    out[t * DM + tid + 256] = d1 * rs * g[tid + 256] + b[tid + 256];
    out[t * DM + tid + 512] = d2 * rs * g[tid + 512] + b[tid + 512];
}

// ---------------- tf32 tensor-core GEMM ----------------
// C[M,N] = A[M,K] @ Bt[N,K]^T  (+bias) (+accum)
// Block tile 128x128, BK=16, 256 threads = 8 warps (2m x 4n), warp tile 64x32.
// mma.sync.m16n8k8 tf32. cp.async double buffered. XOR granule swizzle.
template<bool BIAS, bool ACCUM>
__global__ __launch_bounds__(256) void mma_gemm(
    const float* __restrict__ A, const float* __restrict__ Bt,
    const float* __restrict__ bias, float* __restrict__ C,
    int N, int K) {
    __shared__ float As[2][128][16];
    __shared__ float Bs[2][128][16];
    int tid = threadIdx.x;
    int m0 = blockIdx.y * 128, n0 = blockIdx.x * 128;
    int warp = tid >> 5, lane = tid & 31;
    int wm = warp >> 2, wn = warp & 3;
    int g = lane >> 2, q = lane & 3;
    int lrow = tid >> 2, lq = tid & 3;

    float acc[4][4][4];
#pragma unroll
    for (int i = 0; i < 4; i++)
#pragma unroll
        for (int j = 0; j < 4; j++)
#pragma unroll
            for (int r = 0; r < 4; r++) acc[i][j][r] = 0.f;

    const float* Ag0 = A  + (size_t)(m0 + lrow) * K + lq * 4;
    const float* Ag1 = A  + (size_t)(m0 + lrow + 64) * K + lq * 4;
    const float* Bg0 = Bt + (size_t)(n0 + lrow) * K + lq * 4;
    const float* Bg1 = Bt + (size_t)(n0 + lrow + 64) * K + lq * 4;
    int sw = (lq ^ ((lrow >> 1) & 3)) * 4;   // same for row and row+64

    const int KT = K >> 4;

    // prologue
    cpasync16(&As[0][lrow][sw],      Ag0);
    cpasync16(&As[0][lrow + 64][sw], Ag1);
    cpasync16(&Bs[0][lrow][sw],      Bg0);
    cpasync16(&Bs[0][lrow + 64][sw], Bg1);
    asm volatile("cp.async.commit_group;");

    for (int kt = 0; kt < KT; kt++) {
        int cur = kt & 1;
        if (kt + 1 < KT) {
            int k0 = (kt + 1) << 4;
            int nb = cur ^ 1;
            cpasync16(&As[nb][lrow][sw],      Ag0 + k0);
            cpasync16(&As[nb][lrow + 64][sw], Ag1 + k0);
            cpasync16(&Bs[nb][lrow][sw],      Bg0 + k0);
            cpasync16(&Bs[nb][lrow + 64][sw], Bg1 + k0);
            asm volatile("cp.async.commit_group;");
            asm volatile("cp.async.wait_group 1;");
        } else {
            asm volatile("cp.async.wait_group 0;");
        }
        __syncthreads();

#pragma unroll
        for (int ks = 0; ks < 2; ks++) {
            unsigned af[4][4], bf[4][2];
#pragma unroll
            for (int mt = 0; mt < 4; mt++) {
                int r  = wm * 64 + mt * 16 + g;
                int r8 = r + 8;
                int s0 = (r  >> 1) & 3;
                int s8 = (r8 >> 1) & 3;
                af[mt][0] = tf32r(As[cur][r ][((2 * ks)     ^ s0) * 4 + q]);
                af[mt][1] = tf32r(As[cur][r8][((2 * ks)     ^ s8) * 4 + q]);
                af[mt][2] = tf32r(As[cur][r ][((2 * ks + 1) ^ s0) * 4 + q]);
                af[mt][3] = tf32r(As[cur][r8][((2 * ks + 1) ^ s8) * 4 + q]);
            }
#pragma unroll
            for (int nt = 0; nt < 4; nt++) {
                int n = wn * 32 + nt * 8 + g;
                int sn = (n >> 1) & 3;
                bf[nt][0] = tf32r(Bs[cur][n][((2 * ks)     ^ sn) * 4 + q]);
                bf[nt][1] = tf32r(Bs[cur][n][((2 * ks + 1) ^ sn) * 4 + q]);
            }
#pragma unroll
            for (int mt = 0; mt < 4; mt++)
#pragma unroll
                for (int nt = 0; nt < 4; nt++)
                    mma8(acc[mt][nt], af[mt], bf[nt]);
        }
        __syncthreads();
    }

    // epilogue
#pragma unroll
    for (int mt = 0; mt < 4; mt++) {
        int r = m0 + wm * 64 + mt * 16 + g;
#pragma unroll
        for (int nt = 0; nt < 4; nt++) {
            int cc = n0 + wn * 32 + nt * 8 + 2 * q;
            float2 v0 = make_float2(acc[mt][nt][0], acc[mt][nt][1]);
            float2 v1 = make_float2(acc[mt][nt][2], acc[mt][nt][3]);
            if (BIAS) {
                float bx = bias[cc], by = bias[cc + 1];
                v0.x += bx; v0.y += by; v1.x += bx; v1.y += by;
            }
            float* p0 = C + (size_t)r * N + cc;
            float* p1 = C + (size_t)(r + 8) * N + cc;
            if (ACCUM) {
                float2 o0 = *(const float2*)p0, o1 = *(const float2*)p1;
                v0.x += o0.x; v0.y += o0.y; v1.x += o1.x; v1.y += o1.y;
            }
            *(float2*)p0 = v0;
            *(float2*)p1 = v1;
        }
    }
}

// ---------------- attention (exp-space causal linear attention) ----------------
__global__ __launch_bounds__(256) void attn_kernel(
    const float* __restrict__ qkv, float* __restrict__ att) {
    int c = blockIdx.x;
    int h = blockIdx.y;
    int tid = threadIdx.x;

    __shared__ float EQ[64][36];
    __shared__ float EK[64][36];
    __shared__ float EV[64][36];
    __shared__ float W [64][65];

    int t0 = c * 64;
    for (int e = tid; e < 64 * 32; e += 256) {
        int r = e >> 5, k = e & 31;
        EQ[r][k] = expf(qkv[(size_t)(t0 + r) * QKV_OUT + h * 96 + k]);
    }

    float S[8];
#pragma unroll
    for (int u = 0; u < 8; u++) S[u] = 0.f;
    float z = 0.f;

    int rr = tid >> 2;
    int q4 = tid & 3;
    int tc = q4 * 8;

    __syncthreads();

    for (int sc = 0; sc <= c; sc++) {
        int s0 = sc * 64;
        for (int e = tid; e < 64 * 32; e += 256) {
            int r = e >> 5, k = e & 31;
            const float* p = &qkv[(size_t)(s0 + r) * QKV_OUT + h * 96 + 32 + k];
            EK[r][k] = expf(p[0]);
            EV[r][k] = expf(p[32]);
        }
        __syncthreads();

        {
            float accw[16];
#pragma unroll
            for (int ss = 0; ss < 16; ss++) accw[ss] = 0.f;
#pragma unroll
            for (int k0 = 0; k0 < 32; k0 += 4) {
                float4 qv = *(const float4*)&EQ[rr][k0];
#pragma unroll
                for (int ss = 0; ss < 16; ss++) {
                    float4 e = *(const float4*)&EK[4 * ss + q4][k0];
                    accw[ss] += qv.x * e.x + qv.y * e.y + qv.z * e.z + qv.w * e.w;
                }
            }
            bool diag = (sc == c);
#pragma unroll
            for (int ss = 0; ss < 16; ss++) {
                int s = 4 * ss + q4;
                W[rr][s] = (diag && s > rr) ? 0.f : accw[ss];
            }
        }
        __syncthreads();

#pragma unroll 4
        for (int s = 0; s < 64; s++) {
            float w = W[rr][s];
            z += w;
            float4 e0 = *(const float4*)&EV[s][tc];
            float4 e1 = *(const float4*)&EV[s][tc + 4];
            S[0] += w * e0.x; S[1] += w * e0.y; S[2] += w * e0.z; S[3] += w * e0.w;
            S[4] += w * e1.x; S[5] += w * e1.y; S[6] += w * e1.z; S[7] += w * e1.w;
        }
        __syncthreads();
    }

    float lz = logf(z);
    float* o = &att[(size_t)(t0 + rr) * DM + h * 32 + tc];
#pragma unroll
    for (int u = 0; u < 8; u++) o[u] = logf(S[u]) - lz;
}

// ---------------- GLU ----------------
__global__ void glu_kernel(const float* __restrict__ zin, float* __restrict__ zout) {
    int t = blockIdx.x, d = threadIdx.x;
    float a = zin[t * FF_IN + d];
    float b = zin[t * FF_IN + DM + d];
    zout[t * DM + d] = a * (1.f / (1.f + expf(-b)));
}

// ---------------- launch ----------------
extern "C" void kernel_launch(void* const* d_in, const int* in_sizes, int n_in,
                              void* d_out, int out_size) {
    const int*   tok     = (const int*)  d_in[0];
    const float* embed_w = (const float*)d_in[1];
    const float* pos_w   = (const float*)d_in[2];
    const float* pos_b   = (const float*)d_in[3];
    const float* ln1_g   = (const float*)d_in[4];
    const float* ln1_b   = (const float*)d_in[5];
    const float* qkv_w   = (const float*)d_in[6];
    const float* qkv_b   = (const float*)d_in[7];
    const float* ff_w1   = (const float*)d_in[8];
    const float* ff_b1   = (const float*)d_in[9];
    const float* ff_w2   = (const float*)d_in[10];
    const float* lnf_g   = (const float*)d_in[11];
    const float* lnf_b   = (const float*)d_in[12];

    float *x, *ln, *buf, *att, *z, *z2, *wT;
    cudaGetSymbolAddress((void**)&x,   g_x);
    cudaGetSymbolAddress((void**)&ln,  g_ln);
    cudaGetSymbolAddress((void**)&buf, g_buf);
    cudaGetSymbolAddress((void**)&att, g_att);
    cudaGetSymbolAddress((void**)&z,   g_z);
    cudaGetSymbolAddress((void**)&z2,  g_z2);
    cudaGetSymbolAddress((void**)&wT,  g_wT);

    float* qkvT = wT + QKVT_OFF;
    float* ff1T = wT + FF1T_OFF;
    float* ff2T = wT + FF2T_OFF;
    float* posT = wT + POST_OFF;

    cudaStream_t st = cudaStreamPerThread;
    dim3 tb(32, 8);

    // weight transposes: (K,N) -> (N,K)
    transpose_kernel<<<dim3(QKV_OUT / 32, DM / 32, NL), tb, 0, st>>>(qkv_w, qkvT, DM, QKV_OUT);
    transpose_kernel<<<dim3(FF_IN / 32,  DM / 32, NL), tb, 0, st>>>(ff_w1, ff1T, DM, FF_IN);
    transpose_kernel<<<dim3(DM / 32,     DM / 32, NL), tb, 0, st>>>(ff_w2, ff2T, DM, DM);
    transpose_kernel<<<dim3(FF_IN / 32,  DM / 32, 1 ), tb, 0, st>>>(pos_w, posT, DM, FF_IN);

    // x = embed_w[token_ids]
    embed_kernel<<<SEQ, DM, 0, st>>>(tok, embed_w, x);

    // h = x @ pos_w + pos_b
    mma_gemm<true, false><<<dim3(FF_IN / 128, SEQ / 128), 256, 0, st>>>(
        x, posT, pos_b, buf, FF_IN, DM);

    // x += positional recurrence
    pos_scan_kernel<<<6, 128, 0, st>>>(buf, x);

    for (int l = 0; l < NL; l++) {
        layernorm_kernel<<<SEQ, 256, 0, st>>>(x, ln1_g + l * DM, ln1_b + l * DM, ln);

        mma_gemm<true, false><<<dim3(QKV_OUT / 128, SEQ / 128), 256, 0, st>>>(
            ln, qkvT + (size_t)l * QKV_OUT * DM, qkv_b + l * QKV_OUT, buf, QKV_OUT, DM);

        attn_kernel<<<dim3(16, NH), 256, 0, st>>>(buf, att);

        mma_gemm<true, false><<<dim3(FF_IN / 128, SEQ / 128), 256, 0, st>>>(
            att, ff1T + (size_t)l * FF_IN * DM, ff_b1 + l * FF_IN, z, FF_IN, DM);

        glu_kernel<<<SEQ, DM, 0, st>>>(z, z2);

        mma_gemm<false, true><<<dim3(DM / 128, SEQ / 128), 256, 0, st>>>(
            z2, ff2T + (size_t)l * DM * DM, nullptr, x, DM, DM);
    }

    layernorm_kernel<<<SEQ, 256, 0, st>>>(x, lnf_g, lnf_b, ln);

    // logits = ln @ embed_w^T  (embed_w is already (V, D) = (N, K))
    mma_gemm<false, false><<<dim3(VSZ / 128, SEQ / 128), 256, 0, st>>>(
        ln, embed_w, nullptr, (float*)d_out, VSZ, DM);
}